// round 6
// baseline (speedup 1.0000x reference)
#include <cuda_runtime.h>
#include <cuda_bf16.h>
#include <math.h>
#include <stdint.h>

#define B_ 2
#define T_ 3136
#define DIM_ 768
#define HEADS_ 12
#define DH_ 64
#define NPATCH_ 196
#define QKVDIM_ 2304
#define ROWS_ (B_ * T_)           // 6272
#define SCALE_ 0.125f             // 64^-0.5

// ---------------- scratch (device globals; no allocation allowed) ----------
__device__ float g_xn[ROWS_ * DIM_];      // LayerNorm output
__device__ float g_qkv[ROWS_ * QKVDIM_];  // QKV projection
__device__ float g_att[ROWS_ * DIM_];     // attention output (pre out-proj)

// ---------------- helpers --------------------------------------------------
__device__ __forceinline__ uint32_t f2tf32(float x) {
    uint32_t y;
    asm("cvt.rna.tf32.f32 %0, %1;" : "=r"(y) : "f"(x));
    return y;
}

__device__ __forceinline__ void mma_tf32(float* c, const uint32_t* a, const uint32_t* b) {
    asm volatile(
        "mma.sync.aligned.m16n8k8.row.col.f32.tf32.tf32.f32 "
        "{%0,%1,%2,%3}, {%4,%5,%6,%7}, {%8,%9}, {%0,%1,%2,%3};\n"
        : "+f"(c[0]), "+f"(c[1]), "+f"(c[2]), "+f"(c[3])
        : "r"(a[0]), "r"(a[1]), "r"(a[2]), "r"(a[3]), "r"(b[0]), "r"(b[1]));
}

// ---------------- LayerNorm: one row per block, 192 threads (float4) -------
__global__ void __launch_bounds__(192) ln_kernel(
    const float* __restrict__ x, const float* __restrict__ gamma,
    const float* __restrict__ beta, float* __restrict__ out)
{
    int row = blockIdx.x;
    int t = threadIdx.x;  // 0..191, 768/4 = 192 float4 per row
    float4 v = reinterpret_cast<const float4*>(x + (size_t)row * DIM_)[t];
    float s  = v.x + v.y + v.z + v.w;
    float ss = v.x * v.x + v.y * v.y + v.z * v.z + v.w * v.w;
    #pragma unroll
    for (int o = 16; o > 0; o >>= 1) {
        s  += __shfl_xor_sync(0xffffffffu, s, o);
        ss += __shfl_xor_sync(0xffffffffu, ss, o);
    }
    __shared__ float sh[12];
    int w = t >> 5;
    if ((t & 31) == 0) { sh[w] = s; sh[6 + w] = ss; }
    __syncthreads();
    float S = 0.f, SS = 0.f;
    #pragma unroll
    for (int i = 0; i < 6; i++) { S += sh[i]; SS += sh[6 + i]; }
    float mean = S * (1.0f / DIM_);
    float var  = SS * (1.0f / DIM_) - mean * mean;
    float rstd = rsqrtf(var + 1e-5f);
    float4 g  = reinterpret_cast<const float4*>(gamma)[t];
    float4 bb = reinterpret_cast<const float4*>(beta)[t];
    float4 r;
    r.x = (v.x - mean) * rstd * g.x + bb.x;
    r.y = (v.y - mean) * rstd * g.y + bb.y;
    r.z = (v.z - mean) * rstd * g.z + bb.z;
    r.w = (v.w - mean) * rstd * g.w + bb.w;
    reinterpret_cast<float4*>(out + (size_t)row * DIM_)[t] = r;
}

// ---------------- tf32 tensor-core GEMM: C = A @ B (+bias) -----------------
// 128x128x16 block tile, 256 threads / 8 warps (4x2), warp tile 32x64.
// As stored [k][m] (stride 136), Bs stored [k][n] (stride 136): conflict-free
// fragment loads. M, N, K multiples of tile sizes — no bounds checks.
#define GBK 16
#define GSTR 136
__global__ void __launch_bounds__(256, 2) gemm_tf32(
    const float* __restrict__ A, const float* __restrict__ Bm,
    const float* __restrict__ bias, float* __restrict__ C,
    int M, int N, int K)
{
    __shared__ uint32_t As[2][GBK][GSTR];
    __shared__ uint32_t Bs[2][GBK][GSTR];
    int tid = threadIdx.x;
    int lane = tid & 31, warp = tid >> 5;
    int wm = (warp >> 1) * 32, wn = (warp & 1) * 64;
    int bm = blockIdx.y * 128, bn = blockIdx.x * 128;

    int arow = tid >> 1, ak = (tid & 1) * 8;       // A: 128 rows x 16, 8/thread
    int brow = tid >> 4, bcol = (tid & 15) * 8;    // B: 16 rows x 128, 8/thread
    const float* Aptr = A + (size_t)(bm + arow) * K + ak;
    const float* Bptr = Bm + (size_t)brow * N + bn + bcol;

    float acc[2][8][4];
    #pragma unroll
    for (int i = 0; i < 2; i++)
        #pragma unroll
        for (int j = 0; j < 8; j++)
            #pragma unroll
            for (int r = 0; r < 4; r++) acc[i][j][r] = 0.f;

    float4 pa0, pa1, pb0, pb1;
    pa0 = *reinterpret_cast<const float4*>(Aptr);
    pa1 = *reinterpret_cast<const float4*>(Aptr + 4);
    pb0 = *reinterpret_cast<const float4*>(Bptr);
    pb1 = *reinterpret_cast<const float4*>(Bptr + 4);

    // store tile 0 into buf 0
    {
        As[0][ak + 0][arow] = f2tf32(pa0.x); As[0][ak + 1][arow] = f2tf32(pa0.y);
        As[0][ak + 2][arow] = f2tf32(pa0.z); As[0][ak + 3][arow] = f2tf32(pa0.w);
        As[0][ak + 4][arow] = f2tf32(pa1.x); As[0][ak + 5][arow] = f2tf32(pa1.y);
        As[0][ak + 6][arow] = f2tf32(pa1.z); As[0][ak + 7][arow] = f2tf32(pa1.w);
        uint4 u0 = make_uint4(f2tf32(pb0.x), f2tf32(pb0.y), f2tf32(pb0.z), f2tf32(pb0.w));
        uint4 u1 = make_uint4(f2tf32(pb1.x), f2tf32(pb1.y), f2tf32(pb1.z), f2tf32(pb1.w));
        *reinterpret_cast<uint4*>(&Bs[0][brow][bcol])     = u0;
        *reinterpret_cast<uint4*>(&Bs[0][brow][bcol + 4]) = u1;
    }
    __syncthreads();

    int KT = K / GBK;
    int buf = 0;
    for (int kt = 0; kt < KT; kt++) {
        if (kt + 1 < KT) {
            int k0 = (kt + 1) * GBK;
            pa0 = *reinterpret_cast<const float4*>(Aptr + k0);
            pa1 = *reinterpret_cast<const float4*>(Aptr + k0 + 4);
            pb0 = *reinterpret_cast<const float4*>(Bptr + (size_t)k0 * N);
            pb1 = *reinterpret_cast<const float4*>(Bptr + (size_t)k0 * N + 4);
        }
        #pragma unroll
        for (int kk = 0; kk < 2; kk++) {
            int kd = kk * 8 + (lane & 3);
            uint32_t af[2][4], bf[8][2];
            #pragma unroll
            for (int mt = 0; mt < 2; mt++) {
                int m = wm + mt * 16 + (lane >> 2);
                af[mt][0] = As[buf][kd][m];
                af[mt][1] = As[buf][kd][m + 8];
                af[mt][2] = As[buf][kd + 4][m];
                af[mt][3] = As[buf][kd + 4][m + 8];
            }
            #pragma unroll
            for (int nt = 0; nt < 8; nt++) {
                int n = wn + nt * 8 + (lane >> 2);
                bf[nt][0] = Bs[buf][kd][n];
                bf[nt][1] = Bs[buf][kd + 4][n];
            }
            #pragma unroll
            for (int mt = 0; mt < 2; mt++)
                #pragma unroll
                for (int nt = 0; nt < 8; nt++)
                    mma_tf32(acc[mt][nt], af[mt], bf[nt]);
        }
        if (kt + 1 < KT) {
            int nb = buf ^ 1;
            As[nb][ak + 0][arow] = f2tf32(pa0.x); As[nb][ak + 1][arow] = f2tf32(pa0.y);
            As[nb][ak + 2][arow] = f2tf32(pa0.z); As[nb][ak + 3][arow] = f2tf32(pa0.w);
            As[nb][ak + 4][arow] = f2tf32(pa1.x); As[nb][ak + 5][arow] = f2tf32(pa1.y);
            As[nb][ak + 6][arow] = f2tf32(pa1.z); As[nb][ak + 7][arow] = f2tf32(pa1.w);
            uint4 u0 = make_uint4(f2tf32(pb0.x), f2tf32(pb0.y), f2tf32(pb0.z), f2tf32(pb0.w));
            uint4 u1 = make_uint4(f2tf32(pb1.x), f2tf32(pb1.y), f2tf32(pb1.z), f2tf32(pb1.w));
            *reinterpret_cast<uint4*>(&Bs[nb][brow][bcol])     = u0;
            *reinterpret_cast<uint4*>(&Bs[nb][brow][bcol + 4]) = u1;
        }
        __syncthreads();
        buf ^= 1;
    }

    // epilogue
    #pragma unroll
    for (int mt = 0; mt < 2; mt++) {
        int r0 = bm + wm + mt * 16 + (lane >> 2);
        #pragma unroll
        for (int nt = 0; nt < 8; nt++) {
            int col = bn + wn + nt * 8 + 2 * (lane & 3);
            float b0 = 0.f, b1 = 0.f;
            if (bias) { b0 = __ldg(bias + col); b1 = __ldg(bias + col + 1); }
            float2 v0 = make_float2(acc[mt][nt][0] + b0, acc[mt][nt][1] + b1);
            float2 v1 = make_float2(acc[mt][nt][2] + b0, acc[mt][nt][3] + b1);
            *reinterpret_cast<float2*>(C + (size_t)r0 * N + col) = v0;
            *reinterpret_cast<float2*>(C + (size_t)(r0 + 8) * N + col) = v1;
        }
    }
}

// ---------------- tf32 flash attention -------------------------------------
// Block: 256 queries of one (b,h); 256 threads / 8 warps, each warp 32 rows
// (2 m16 tiles). Q fragments live in REGISTERS for the whole kv loop (loaded
// once from gmem). S = Q@K^T via mma; exp + analytic block-causal mask in
// regs; P staged through per-warp-private Ps smem columns; O += P@V via mma.
// Dyn smem (uint32 words):
//   Ps [64][264]  ([j][q])  off 0       (16896 words)
//   Ks [64][68]   ([j][d])  off 16896   (4352)
//   Vs [64][72]   ([j][d])  off 21248   (4608)
// total 25856 words = 103424 bytes
#define ATT_SMEM_BYTES 103424
#define QTILE 256
__global__ void __launch_bounds__(256, 1) attn_tf32(
    const float* __restrict__ qkv, float* __restrict__ att)
{
    extern __shared__ uint32_t sm[];
    uint32_t* Ps = sm;
    uint32_t* Ks = sm + 16896;
    uint32_t* Vs = sm + 21248;

    int tid = threadIdx.x, lane = tid & 31, warp = tid >> 5;
    int qt = (gridDim.x - 1) - blockIdx.x;   // heavy (long-kv) tiles first
    int h = blockIdx.y, b = blockIdx.z;
    const float* base = qkv + (size_t)b * T_ * QKVDIM_ + h * DH_;

    // ---- load Q fragments straight into registers (once) ----
    // af layout for m16n8k8: a0=(r, k) a1=(r+8, k) a2=(r, k+4) a3=(r+8, k+4)
    // with r = lane>>2 (+ tile offsets), k = lane&3 (+ 8*kk)
    uint32_t qf[2][8][4];
    #pragma unroll
    for (int mt = 0; mt < 2; mt++) {
        int r0 = qt * QTILE + warp * 32 + mt * 16 + (lane >> 2);
        int r0c = min(r0, T_ - 1), r1c = min(r0 + 8, T_ - 1);
        const float* q0p = base + (size_t)r0c * QKVDIM_;
        const float* q1p = base + (size_t)r1c * QKVDIM_;
        #pragma unroll
        for (int kk = 0; kk < 8; kk++) {
            int k = kk * 8 + (lane & 3);
            qf[mt][kk][0] = f2tf32(__ldg(q0p + k));
            qf[mt][kk][1] = f2tf32(__ldg(q1p + k));
            qf[mt][kk][2] = f2tf32(__ldg(q0p + k + 4));
            qf[mt][kk][3] = f2tf32(__ldg(q1p + k + 4));
        }
    }

    // per-thread row kv lengths (block-causal): kvlen(q) = (q/196 + 1)*196
    int len0[2], len1[2];
    #pragma unroll
    for (int mt = 0; mt < 2; mt++) {
        int r = qt * QTILE + warp * 32 + mt * 16 + (lane >> 2);
        len0[mt] = (r < T_)     ? ((r / NPATCH_) + 1) * NPATCH_ : 0;
        len1[mt] = (r + 8 < T_) ? (((r + 8) / NPATCH_) + 1) * NPATCH_ : 0;
    }
    int qlast = min(qt * QTILE + QTILE - 1, T_ - 1);
    int kvmax = ((qlast / NPATCH_) + 1) * NPATCH_;

    float oacc[2][8][4];
    #pragma unroll
    for (int mt = 0; mt < 2; mt++)
        #pragma unroll
        for (int nt = 0; nt < 8; nt++)
            #pragma unroll
            for (int r = 0; r < 4; r++) oacc[mt][nt][r] = 0.f;
    float lacc[2][2] = {{0.f, 0.f}, {0.f, 0.f}};

    for (int k0 = 0; k0 < kvmax; k0 += 64) {
        // cooperative K/V tile load (rows k0..k0+63 always < T), uint4 STS
        #pragma unroll
        for (int p = 0; p < 4; p++) {
            int f = p * 256 + tid;
            int j = f >> 4, d4 = (f & 15) * 4;
            const float* rp = base + (size_t)(k0 + j) * QKVDIM_ + d4;
            float4 k4 = *reinterpret_cast<const float4*>(rp + DIM_);
            float4 v4 = *reinterpret_cast<const float4*>(rp + 2 * DIM_);
            uint4 ku = make_uint4(f2tf32(k4.x), f2tf32(k4.y), f2tf32(k4.z), f2tf32(k4.w));
            uint4 vu = make_uint4(f2tf32(v4.x), f2tf32(v4.y), f2tf32(v4.z), f2tf32(v4.w));
            *reinterpret_cast<uint4*>(Ks + j * 68 + d4) = ku;
            *reinterpret_cast<uint4*>(Vs + j * 72 + d4) = vu;
        }
        __syncthreads();

        // S = Q @ K^T  (this warp's 32 rows x 64 keys); Q from registers
        float sacc[2][8][4];
        #pragma unroll
        for (int mt = 0; mt < 2; mt++)
            #pragma unroll
            for (int nt = 0; nt < 8; nt++)
                #pragma unroll
                for (int r = 0; r < 4; r++) sacc[mt][nt][r] = 0.f;

        #pragma unroll
        for (int kk = 0; kk < 8; kk++) {
            int kd = kk * 8 + (lane & 3);
            uint32_t bf[8][2];
            #pragma unroll
            for (int nt = 0; nt < 8; nt++) {
                int j = nt * 8 + (lane >> 2);
                bf[nt][0] = Ks[j * 68 + kd];
                bf[nt][1] = Ks[j * 68 + kd + 4];
            }
            #pragma unroll
            for (int mt = 0; mt < 2; mt++)
                #pragma unroll
                for (int nt = 0; nt < 8; nt++)
                    mma_tf32(sacc[mt][nt], qf[mt][kk], bf[nt]);
        }

        // exp + mask + row-sum, stage P into per-warp-private Ps columns
        #pragma unroll
        for (int mt = 0; mt < 2; mt++) {
            int qloc = warp * 32 + mt * 16 + (lane >> 2);
            #pragma unroll
            for (int nt = 0; nt < 8; nt++) {
                int jl = nt * 8 + 2 * (lane & 3);
                int jg = k0 + jl;
                float p00 = (jg     < len0[mt]) ? __expf(sacc[mt][nt][0] * SCALE_) : 0.f;
                float p01 = (jg + 1 < len0[mt]) ? __expf(sacc[mt][nt][1] * SCALE_) : 0.f;
                float p10 = (jg     < len1[mt]) ? __expf(sacc[mt][nt][2] * SCALE_) : 0.f;
                float p11 = (jg + 1 < len1[mt]) ? __expf(sacc[mt][nt][3] * SCALE_) : 0.f;
                uint32_t u00 = f2tf32(p00), u01 = f2tf32(p01);
                uint32_t u10 = f2tf32(p10), u11 = f2tf32(p11);
                // accumulate l from the *rounded* P so PV and l agree
                lacc[mt][0] += __uint_as_float(u00) + __uint_as_float(u01);
                lacc[mt][1] += __uint_as_float(u10) + __uint_as_float(u11);
                Ps[jl * 264 + qloc]           = u00;
                Ps[(jl + 1) * 264 + qloc]     = u01;
                Ps[jl * 264 + qloc + 8]       = u10;
                Ps[(jl + 1) * 264 + qloc + 8] = u11;
            }
        }
        __syncwarp();

        // O += P @ V
        #pragma unroll
        for (int kk = 0; kk < 8; kk++) {
            int kd = kk * 8 + (lane & 3);
            uint32_t af[2][4], bf[8][2];
            #pragma unroll
            for (int mt = 0; mt < 2; mt++) {
                int q = warp * 32 + mt * 16 + (lane >> 2);
                af[mt][0] = Ps[kd * 264 + q];
                af[mt][1] = Ps[kd * 264 + q + 8];
                af[mt][2] = Ps[(kd + 4) * 264 + q];
                af[mt][3] = Ps[(kd + 4) * 264 + q + 8];
            }
            #pragma unroll
            for (int nt = 0; nt < 8; nt++) {
                int d = nt * 8 + (lane >> 2);
                bf[nt][0] = Vs[kd * 72 + d];
                bf[nt][1] = Vs[(kd + 4) * 72 + d];
            }
            #pragma unroll
            for (int mt = 0; mt < 2; mt++)
                #pragma unroll
                for (int nt = 0; nt < 8; nt++)
                    mma_tf32(oacc[mt][nt], af[mt], bf[nt]);
        }
        __syncthreads();   // Ks/Vs consumed; safe to overwrite next iter
    }

    // quad-reduce row sums, normalize, store
    float* arow = att + (size_t)b * T_ * DIM_ + h * DH_;
    #pragma unroll
    for (int mt = 0; mt < 2; mt++) {
        float l0 = lacc[mt][0], l1 = lacc[mt][1];
        l0 += __shfl_xor_sync(0xffffffffu, l0, 1);
        l0 += __shfl_xor_sync(0xffffffffu, l0, 2);
        l1 += __shfl_xor_sync(0xffffffffu, l1, 1);
        l1 += __shfl_xor_sync(0xffffffffu, l1, 2);
        float inv0 = 1.f / l0, inv1 = 1.f / l1;
        int q0 = qt * QTILE + warp * 32 + mt * 16 + (lane >> 2);
        #pragma unroll
        for (int nt = 0; nt < 8; nt++) {
            int col = nt * 8 + 2 * (lane & 3);
            if (q0 < T_) {
                float2 v = make_float2(oacc[mt][nt][0] * inv0, oacc[mt][nt][1] * inv0);
                *reinterpret_cast<float2*>(arow + (size_t)q0 * DIM_ + col) = v;
            }
            if (q0 + 8 < T_) {
                float2 v = make_float2(oacc[mt][nt][2] * inv1, oacc[mt][nt][3] * inv1);
                *reinterpret_cast<float2*>(arow + (size_t)(q0 + 8) * DIM_ + col) = v;
            }
        }
    }
}

// ---------------- launch ---------------------------------------------------
extern "C" void kernel_launch(void* const* d_in, const int* in_sizes, int n_in,
                              void* d_out, int out_size)
{
    const float* x     = (const float*)d_in[0];
    const float* gamma = (const float*)d_in[1];
    const float* beta  = (const float*)d_in[2];
    const float* wqkv  = (const float*)d_in[3];
    const float* wout  = (const float*)d_in[4];
    const float* bout  = (const float*)d_in[5];
    // d_in[6] is the bool mask; reproduced analytically in-kernel.
    float* out = (float*)d_out;

    float *xn, *qkv, *att;
    cudaGetSymbolAddress((void**)&xn,  g_xn);
    cudaGetSymbolAddress((void**)&qkv, g_qkv);
    cudaGetSymbolAddress((void**)&att, g_att);

    cudaFuncSetAttribute(attn_tf32, cudaFuncAttributeMaxDynamicSharedMemorySize,
                         ATT_SMEM_BYTES);

    ln_kernel<<<ROWS_, 192>>>(x, gamma, beta, xn);
    gemm_tf32<<<dim3(QKVDIM_ / 128, ROWS_ / 128), 256>>>(xn, wqkv, nullptr, qkv,
                                                         ROWS_, QKVDIM_, DIM_);
    attn_tf32<<<dim3((T_ + QTILE - 1) / QTILE, HEADS_, B_), 256, ATT_SMEM_BYTES>>>(qkv, att);
    gemm_tf32<<<dim3(DIM_ / 128, ROWS_ / 128), 256>>>(att, wout, bout, out,
                                                      ROWS_, DIM_, DIM_);
}

// round 7
// speedup vs baseline: 1.1396x; 1.1396x over previous
#include <cuda_runtime.h>
#include <cuda_bf16.h>
#include <math.h>
#include <stdint.h>

#define B_ 2
#define T_ 3136
#define DIM_ 768
#define HEADS_ 12
#define DH_ 64
#define NPATCH_ 196
#define QKVDIM_ 2304
#define ROWS_ (B_ * T_)           // 6272
#define SCALE_ 0.125f             // 64^-0.5

// ---------------- scratch (device globals; no allocation allowed) ----------
__device__ float g_xn[ROWS_ * DIM_];      // LayerNorm output
__device__ float g_qkv[ROWS_ * QKVDIM_];  // QKV projection
__device__ float g_att[ROWS_ * DIM_];     // attention output (pre out-proj)

// ---------------- helpers --------------------------------------------------
__device__ __forceinline__ uint32_t f2tf32(float x) {
    uint32_t y;
    asm("cvt.rna.tf32.f32 %0, %1;" : "=r"(y) : "f"(x));
    return y;
}

__device__ __forceinline__ void mma_tf32(float* c, const uint32_t* a, const uint32_t* b) {
    asm volatile(
        "mma.sync.aligned.m16n8k8.row.col.f32.tf32.tf32.f32 "
        "{%0,%1,%2,%3}, {%4,%5,%6,%7}, {%8,%9}, {%0,%1,%2,%3};\n"
        : "+f"(c[0]), "+f"(c[1]), "+f"(c[2]), "+f"(c[3])
        : "r"(a[0]), "r"(a[1]), "r"(a[2]), "r"(a[3]), "r"(b[0]), "r"(b[1]));
}

// ---------------- LayerNorm: one row per block, 192 threads (float4) -------
__global__ void __launch_bounds__(192) ln_kernel(
    const float* __restrict__ x, const float* __restrict__ gamma,
    const float* __restrict__ beta, float* __restrict__ out)
{
    int row = blockIdx.x;
    int t = threadIdx.x;  // 0..191, 768/4 = 192 float4 per row
    float4 v = reinterpret_cast<const float4*>(x + (size_t)row * DIM_)[t];
    float s  = v.x + v.y + v.z + v.w;
    float ss = v.x * v.x + v.y * v.y + v.z * v.z + v.w * v.w;
    #pragma unroll
    for (int o = 16; o > 0; o >>= 1) {
        s  += __shfl_xor_sync(0xffffffffu, s, o);
        ss += __shfl_xor_sync(0xffffffffu, ss, o);
    }
    __shared__ float sh[12];
    int w = t >> 5;
    if ((t & 31) == 0) { sh[w] = s; sh[6 + w] = ss; }
    __syncthreads();
    float S = 0.f, SS = 0.f;
    #pragma unroll
    for (int i = 0; i < 6; i++) { S += sh[i]; SS += sh[6 + i]; }
    float mean = S * (1.0f / DIM_);
    float var  = SS * (1.0f / DIM_) - mean * mean;
    float rstd = rsqrtf(var + 1e-5f);
    float4 g  = reinterpret_cast<const float4*>(gamma)[t];
    float4 bb = reinterpret_cast<const float4*>(beta)[t];
    float4 r;
    r.x = (v.x - mean) * rstd * g.x + bb.x;
    r.y = (v.y - mean) * rstd * g.y + bb.y;
    r.z = (v.z - mean) * rstd * g.z + bb.z;
    r.w = (v.w - mean) * rstd * g.w + bb.w;
    reinterpret_cast<float4*>(out + (size_t)row * DIM_)[t] = r;
}

// ---------------- tf32 tensor-core GEMM: C = A @ B (+bias) -----------------
// 128x128x16 block tile, 256 threads / 8 warps (4x2), warp tile 32x64.
// As stored [k][m] (stride 136), Bs stored [k][n] (stride 136): conflict-free
// fragment loads. M, N, K multiples of tile sizes — no bounds checks.
#define GBK 16
#define GSTR 136
__global__ void __launch_bounds__(256, 2) gemm_tf32(
    const float* __restrict__ A, const float* __restrict__ Bm,
    const float* __restrict__ bias, float* __restrict__ C,
    int M, int N, int K)
{
    __shared__ uint32_t As[2][GBK][GSTR];
    __shared__ uint32_t Bs[2][GBK][GSTR];
    int tid = threadIdx.x;
    int lane = tid & 31, warp = tid >> 5;
    int wm = (warp >> 1) * 32, wn = (warp & 1) * 64;
    int bm = blockIdx.y * 128, bn = blockIdx.x * 128;

    int arow = tid >> 1, ak = (tid & 1) * 8;       // A: 128 rows x 16, 8/thread
    int brow = tid >> 4, bcol = (tid & 15) * 8;    // B: 16 rows x 128, 8/thread
    const float* Aptr = A + (size_t)(bm + arow) * K + ak;
    const float* Bptr = Bm + (size_t)brow * N + bn + bcol;

    float acc[2][8][4];
    #pragma unroll
    for (int i = 0; i < 2; i++)
        #pragma unroll
        for (int j = 0; j < 8; j++)
            #pragma unroll
            for (int r = 0; r < 4; r++) acc[i][j][r] = 0.f;

    float4 pa0, pa1, pb0, pb1;
    pa0 = *reinterpret_cast<const float4*>(Aptr);
    pa1 = *reinterpret_cast<const float4*>(Aptr + 4);
    pb0 = *reinterpret_cast<const float4*>(Bptr);
    pb1 = *reinterpret_cast<const float4*>(Bptr + 4);

    // store tile 0 into buf 0
    {
        As[0][ak + 0][arow] = f2tf32(pa0.x); As[0][ak + 1][arow] = f2tf32(pa0.y);
        As[0][ak + 2][arow] = f2tf32(pa0.z); As[0][ak + 3][arow] = f2tf32(pa0.w);
        As[0][ak + 4][arow] = f2tf32(pa1.x); As[0][ak + 5][arow] = f2tf32(pa1.y);
        As[0][ak + 6][arow] = f2tf32(pa1.z); As[0][ak + 7][arow] = f2tf32(pa1.w);
        uint4 u0 = make_uint4(f2tf32(pb0.x), f2tf32(pb0.y), f2tf32(pb0.z), f2tf32(pb0.w));
        uint4 u1 = make_uint4(f2tf32(pb1.x), f2tf32(pb1.y), f2tf32(pb1.z), f2tf32(pb1.w));
        *reinterpret_cast<uint4*>(&Bs[0][brow][bcol])     = u0;
        *reinterpret_cast<uint4*>(&Bs[0][brow][bcol + 4]) = u1;
    }
    __syncthreads();

    int KT = K / GBK;
    int buf = 0;
    for (int kt = 0; kt < KT; kt++) {
        if (kt + 1 < KT) {
            int k0 = (kt + 1) * GBK;
            pa0 = *reinterpret_cast<const float4*>(Aptr + k0);
            pa1 = *reinterpret_cast<const float4*>(Aptr + k0 + 4);
            pb0 = *reinterpret_cast<const float4*>(Bptr + (size_t)k0 * N);
            pb1 = *reinterpret_cast<const float4*>(Bptr + (size_t)k0 * N + 4);
        }
        #pragma unroll
        for (int kk = 0; kk < 2; kk++) {
            int kd = kk * 8 + (lane & 3);
            uint32_t af[2][4], bf[8][2];
            #pragma unroll
            for (int mt = 0; mt < 2; mt++) {
                int m = wm + mt * 16 + (lane >> 2);
                af[mt][0] = As[buf][kd][m];
                af[mt][1] = As[buf][kd][m + 8];
                af[mt][2] = As[buf][kd + 4][m];
                af[mt][3] = As[buf][kd + 4][m + 8];
            }
            #pragma unroll
            for (int nt = 0; nt < 8; nt++) {
                int n = wn + nt * 8 + (lane >> 2);
                bf[nt][0] = Bs[buf][kd][n];
                bf[nt][1] = Bs[buf][kd + 4][n];
            }
            #pragma unroll
            for (int mt = 0; mt < 2; mt++)
                #pragma unroll
                for (int nt = 0; nt < 8; nt++)
                    mma_tf32(acc[mt][nt], af[mt], bf[nt]);
        }
        if (kt + 1 < KT) {
            int nb = buf ^ 1;
            As[nb][ak + 0][arow] = f2tf32(pa0.x); As[nb][ak + 1][arow] = f2tf32(pa0.y);
            As[nb][ak + 2][arow] = f2tf32(pa0.z); As[nb][ak + 3][arow] = f2tf32(pa0.w);
            As[nb][ak + 4][arow] = f2tf32(pa1.x); As[nb][ak + 5][arow] = f2tf32(pa1.y);
            As[nb][ak + 6][arow] = f2tf32(pa1.z); As[nb][ak + 7][arow] = f2tf32(pa1.w);
            uint4 u0 = make_uint4(f2tf32(pb0.x), f2tf32(pb0.y), f2tf32(pb0.z), f2tf32(pb0.w));
            uint4 u1 = make_uint4(f2tf32(pb1.x), f2tf32(pb1.y), f2tf32(pb1.z), f2tf32(pb1.w));
            *reinterpret_cast<uint4*>(&Bs[nb][brow][bcol])     = u0;
            *reinterpret_cast<uint4*>(&Bs[nb][brow][bcol + 4]) = u1;
        }
        __syncthreads();
        buf ^= 1;
    }

    // epilogue
    #pragma unroll
    for (int mt = 0; mt < 2; mt++) {
        int r0 = bm + wm + mt * 16 + (lane >> 2);
        #pragma unroll
        for (int nt = 0; nt < 8; nt++) {
            int col = bn + wn + nt * 8 + 2 * (lane & 3);
            float b0 = 0.f, b1 = 0.f;
            if (bias) { b0 = __ldg(bias + col); b1 = __ldg(bias + col + 1); }
            float2 v0 = make_float2(acc[mt][nt][0] + b0, acc[mt][nt][1] + b1);
            float2 v1 = make_float2(acc[mt][nt][2] + b0, acc[mt][nt][3] + b1);
            *reinterpret_cast<float2*>(C + (size_t)r0 * N + col) = v0;
            *reinterpret_cast<float2*>(C + (size_t)(r0 + 8) * N + col) = v1;
        }
    }
}

// ---------------- tf32 flash attention -------------------------------------
// Block: 128 queries of one (b,h); 256 threads / 8 warps, each warp owns 16
// query rows (ONE m16 tile -> sacc/oacc/qf all small, no spills). Q fragments
// in registers for the whole kv loop. 69KB smem -> 2 blocks/SM -> 16 warps/SM
// resident (4/SMSP latency hiding vs 1/SMSP in the 128-thread version).
// Dyn smem (uint32 words):
//   Ps [64][136]  ([j][q])  off 0       (8704 words)
//   Ks [64][68]   ([j][d])  off 8704    (4352)
//   Vs [64][72]   ([j][d])  off 13056   (4608)
// total 17664 words = 70656 bytes
#define ATT_SMEM_BYTES 70656
#define QTILE 128
__global__ void __launch_bounds__(256, 2) attn_tf32(
    const float* __restrict__ qkv, float* __restrict__ att)
{
    extern __shared__ uint32_t sm[];
    uint32_t* Ps = sm;
    uint32_t* Ks = sm + 8704;
    uint32_t* Vs = sm + 13056;

    int tid = threadIdx.x, lane = tid & 31, warp = tid >> 5;
    int qt = (gridDim.x - 1) - blockIdx.x;   // heavy (long-kv) tiles first
    int h = blockIdx.y, b = blockIdx.z;
    const float* base = qkv + (size_t)b * T_ * QKVDIM_ + h * DH_;

    // ---- load Q fragments straight into registers (once) ----
    // m16n8k8 A-frag: a0=(r,k) a1=(r+8,k) a2=(r,k+4) a3=(r+8,k+4),
    // r = lane>>2, k = lane&3 (+8*kk). This warp's rows: qt*128+warp*16+...
    int r0 = qt * QTILE + warp * 16 + (lane >> 2);
    int r0c = min(r0, T_ - 1), r1c = min(r0 + 8, T_ - 1);
    uint32_t qf[8][4];
    {
        const float* q0p = base + (size_t)r0c * QKVDIM_;
        const float* q1p = base + (size_t)r1c * QKVDIM_;
        #pragma unroll
        for (int kk = 0; kk < 8; kk++) {
            int k = kk * 8 + (lane & 3);
            qf[kk][0] = f2tf32(__ldg(q0p + k));
            qf[kk][1] = f2tf32(__ldg(q1p + k));
            qf[kk][2] = f2tf32(__ldg(q0p + k + 4));
            qf[kk][3] = f2tf32(__ldg(q1p + k + 4));
        }
    }

    // block-causal: kvlen(q) = (q/196 + 1)*196
    int len0 = (r0 < T_)     ? ((r0 / NPATCH_) + 1) * NPATCH_ : 0;
    int len1 = (r0 + 8 < T_) ? (((r0 + 8) / NPATCH_) + 1) * NPATCH_ : 0;
    int qlast = min(qt * QTILE + QTILE - 1, T_ - 1);
    int kvmax = ((qlast / NPATCH_) + 1) * NPATCH_;

    float oacc[8][4];
    #pragma unroll
    for (int nt = 0; nt < 8; nt++)
        #pragma unroll
        for (int r = 0; r < 4; r++) oacc[nt][r] = 0.f;
    float l0acc = 0.f, l1acc = 0.f;

    for (int k0 = 0; k0 < kvmax; k0 += 64) {
        // cooperative K/V tile load (rows k0..k0+63 always < T), uint4 STS
        #pragma unroll
        for (int p = 0; p < 4; p++) {
            int f = p * 256 + tid;
            int j = f >> 4, d4 = (f & 15) * 4;
            const float* rp = base + (size_t)(k0 + j) * QKVDIM_ + d4;
            float4 k4 = *reinterpret_cast<const float4*>(rp + DIM_);
            float4 v4 = *reinterpret_cast<const float4*>(rp + 2 * DIM_);
            uint4 ku = make_uint4(f2tf32(k4.x), f2tf32(k4.y), f2tf32(k4.z), f2tf32(k4.w));
            uint4 vu = make_uint4(f2tf32(v4.x), f2tf32(v4.y), f2tf32(v4.z), f2tf32(v4.w));
            *reinterpret_cast<uint4*>(Ks + j * 68 + d4) = ku;
            *reinterpret_cast<uint4*>(Vs + j * 72 + d4) = vu;
        }
        __syncthreads();

        // S = Q @ K^T  (this warp's 16 rows x 64 keys); Q from registers
        float sacc[8][4];
        #pragma unroll
        for (int nt = 0; nt < 8; nt++)
            #pragma unroll
            for (int r = 0; r < 4; r++) sacc[nt][r] = 0.f;

        #pragma unroll
        for (int kk = 0; kk < 8; kk++) {
            int kd = kk * 8 + (lane & 3);
            uint32_t bf[8][2];
            #pragma unroll
            for (int nt = 0; nt < 8; nt++) {
                int j = nt * 8 + (lane >> 2);
                bf[nt][0] = Ks[j * 68 + kd];
                bf[nt][1] = Ks[j * 68 + kd + 4];
            }
            #pragma unroll
            for (int nt = 0; nt < 8; nt++)
                mma_tf32(sacc[nt], qf[kk], bf[nt]);
        }

        // exp + mask + row-sum, stage P into this warp's private Ps columns
        int qloc = warp * 16 + (lane >> 2);
        #pragma unroll
        for (int nt = 0; nt < 8; nt++) {
            int jl = nt * 8 + 2 * (lane & 3);
            int jg = k0 + jl;
            float p00 = (jg     < len0) ? __expf(sacc[nt][0] * SCALE_) : 0.f;
            float p01 = (jg + 1 < len0) ? __expf(sacc[nt][1] * SCALE_) : 0.f;
            float p10 = (jg     < len1) ? __expf(sacc[nt][2] * SCALE_) : 0.f;
            float p11 = (jg + 1 < len1) ? __expf(sacc[nt][3] * SCALE_) : 0.f;
            uint32_t u00 = f2tf32(p00), u01 = f2tf32(p01);
            uint32_t u10 = f2tf32(p10), u11 = f2tf32(p11);
            // accumulate l from the *rounded* P so PV and l agree
            l0acc += __uint_as_float(u00) + __uint_as_float(u01);
            l1acc += __uint_as_float(u10) + __uint_as_float(u11);
            Ps[jl * 136 + qloc]           = u00;
            Ps[(jl + 1) * 136 + qloc]     = u01;
            Ps[jl * 136 + qloc + 8]       = u10;
            Ps[(jl + 1) * 136 + qloc + 8] = u11;
        }
        __syncwarp();

        // O += P @ V
        #pragma unroll
        for (int kk = 0; kk < 8; kk++) {
            int kd = kk * 8 + (lane & 3);
            uint32_t af[4], bf[8][2];
            af[0] = Ps[kd * 136 + qloc];
            af[1] = Ps[kd * 136 + qloc + 8];
            af[2] = Ps[(kd + 4) * 136 + qloc];
            af[3] = Ps[(kd + 4) * 136 + qloc + 8];
            #pragma unroll
            for (int nt = 0; nt < 8; nt++) {
                int d = nt * 8 + (lane >> 2);
                bf[nt][0] = Vs[kd * 72 + d];
                bf[nt][1] = Vs[(kd + 4) * 72 + d];
            }
            #pragma unroll
            for (int nt = 0; nt < 8; nt++)
                mma_tf32(oacc[nt], af, bf[nt]);
        }
        __syncthreads();   // Ks/Vs consumed; safe to overwrite next iter
    }

    // quad-reduce row sums, normalize, store
    float* arow = att + (size_t)b * T_ * DIM_ + h * DH_;
    float l0 = l0acc, l1 = l1acc;
    l0 += __shfl_xor_sync(0xffffffffu, l0, 1);
    l0 += __shfl_xor_sync(0xffffffffu, l0, 2);
    l1 += __shfl_xor_sync(0xffffffffu, l1, 1);
    l1 += __shfl_xor_sync(0xffffffffu, l1, 2);
    float inv0 = 1.f / l0, inv1 = 1.f / l1;
    #pragma unroll
    for (int nt = 0; nt < 8; nt++) {
        int col = nt * 8 + 2 * (lane & 3);
        if (r0 < T_) {
            float2 v = make_float2(oacc[nt][0] * inv0, oacc[nt][1] * inv0);
            *reinterpret_cast<float2*>(arow + (size_t)r0 * DIM_ + col) = v;
        }
        if (r0 + 8 < T_) {
            float2 v = make_float2(oacc[nt][2] * inv1, oacc[nt][3] * inv1);
            *reinterpret_cast<float2*>(arow + (size_t)(r0 + 8) * DIM_ + col) = v;
        }
    }
}

// ---------------- launch ---------------------------------------------------
extern "C" void kernel_launch(void* const* d_in, const int* in_sizes, int n_in,
                              void* d_out, int out_size)
{
    const float* x     = (const float*)d_in[0];
    const float* gamma = (const float*)d_in[1];
    const float* beta  = (const float*)d_in[2];
    const float* wqkv  = (const float*)d_in[3];
    const float* wout  = (const float*)d_in[4];
    const float* bout  = (const float*)d_in[5];
    // d_in[6] is the bool mask; reproduced analytically in-kernel.
    float* out = (float*)d_out;

    float *xn, *qkv, *att;
    cudaGetSymbolAddress((void**)&xn,  g_xn);
    cudaGetSymbolAddress((void**)&qkv, g_qkv);
    cudaGetSymbolAddress((void**)&att, g_att);

    cudaFuncSetAttribute(attn_tf32, cudaFuncAttributeMaxDynamicSharedMemorySize,
                         ATT_SMEM_BYTES);

    ln_kernel<<<ROWS_, 192>>>(x, gamma, beta, xn);
    gemm_tf32<<<dim3(QKVDIM_ / 128, ROWS_ / 128), 256>>>(xn, wqkv, nullptr, qkv,
                                                         ROWS_, QKVDIM_, DIM_);
    attn_tf32<<<dim3((T_ + QTILE - 1) / QTILE, HEADS_, B_), 256, ATT_SMEM_BYTES>>>(qkv, att);
    gemm_tf32<<<dim3(DIM_ / 128, ROWS_ / 128), 256>>>(att, wout, bout, out,
                                                      ROWS_, DIM_, DIM_);
}